// round 2
// baseline (speedup 1.0000x reference)
#include <cuda_runtime.h>
#include <math_constants.h>

#define N_NODES 100000
#define E_EDGES 1600000
#define D 128

// ---------------- scratch (static device globals; no runtime alloc) ---------
__device__ float g_feat[N_NODES * D];     // projected features     (51.2 MB)
__device__ float g_el[N_NODES];           // src attention logits
__device__ float g_er[N_NODES];           // dst attention logits
__device__ float g_ex[E_EDGES];           // exp(edge score)        (6.4 MB)
__device__ float g_denom[N_NODES];        // softmax denominator
__device__ int   g_cnt[N_NODES];          // in-degree histogram
__device__ int   g_off[N_NODES];          // CSR offsets
__device__ int   g_cur[N_NODES];          // scatter cursors
__device__ int   g_ssrc[E_EDGES];         // CSR: src id per slot
__device__ float g_sw[E_EDGES];           // CSR: exp weight per slot

// ---------------- K1: feat = h @ W  (16 rows per block, 128 threads) --------
__global__ void __launch_bounds__(128)
gemm_kernel(const float* __restrict__ h, const float* __restrict__ W) {
    __shared__ float hs[16][D];
    const int t = threadIdx.x;          // output column
    const int row0 = blockIdx.x * 16;

    #pragma unroll
    for (int r = 0; r < 16; r++)
        hs[r][t] = h[(row0 + r) * D + t];
    __syncthreads();

    float acc[16];
    #pragma unroll
    for (int r = 0; r < 16; r++) acc[r] = 0.f;

    #pragma unroll 4
    for (int k = 0; k < D; k++) {
        const float wv = __ldg(&W[k * D + t]);
        #pragma unroll
        for (int r = 0; r < 16; r++)
            acc[r] = fmaf(hs[r][k], wv, acc[r]);
    }

    #pragma unroll
    for (int r = 0; r < 16; r++)
        g_feat[(row0 + r) * D + t] = acc[r];
}

// ---------------- K2: el/er = feat @ attn_{l,r}  (warp per node) ------------
__global__ void __launch_bounds__(256)
elr_kernel(const float* __restrict__ attn_l, const float* __restrict__ attn_r) {
    const int warp = (blockIdx.x * blockDim.x + threadIdx.x) >> 5;
    const int lane = threadIdx.x & 31;
    if (warp >= N_NODES) return;

    const float4 f  = reinterpret_cast<const float4*>(g_feat)[warp * 32 + lane];
    const float4 al = reinterpret_cast<const float4*>(attn_l)[lane];
    const float4 ar = reinterpret_cast<const float4*>(attn_r)[lane];
    float sl = f.x * al.x + f.y * al.y + f.z * al.z + f.w * al.w;
    float sr = f.x * ar.x + f.y * ar.y + f.z * ar.z + f.w * ar.w;
    #pragma unroll
    for (int o = 16; o; o >>= 1) {
        sl += __shfl_down_sync(0xffffffffu, sl, o);
        sr += __shfl_down_sync(0xffffffffu, sr, o);
    }
    if (lane == 0) { g_el[warp] = sl; g_er[warp] = sr; }
}

// ---------------- K3: zero per-node accumulators ----------------------------
__global__ void __launch_bounds__(256)
init_kernel() {
    const int i = blockIdx.x * blockDim.x + threadIdx.x;
    if (i >= N_NODES) return;
    g_denom[i] = 0.f;
    g_cnt[i]   = 0;
    g_cur[i]   = 0;
}

// ---------------- K4: edge scores + denom + degree histogram ---------------
__global__ void __launch_bounds__(256)
edge_kernel(const int* __restrict__ src, const int* __restrict__ dst) {
    const int e = blockIdx.x * blockDim.x + threadIdx.x;
    if (e >= E_EDGES) return;
    const int s = src[e];
    const int d = dst[e];
    float x = g_el[s] + g_er[d];
    x = (x > 0.f) ? x : 0.2f * x;           // leaky relu
    const float ex = __expf(x);             // no max-subtraction needed (|x|<~12)
    g_ex[e] = ex;
    atomicAdd(&g_denom[d], ex);
    atomicAdd(&g_cnt[d], 1);
}

// ---------------- K5: exclusive scan over g_cnt (single block, 512 thr) -----
#define SCAN_T 512
#define SCAN_CHUNK ((N_NODES + SCAN_T - 1) / SCAN_T)   // 196
__global__ void __launch_bounds__(SCAN_T)
scan_kernel() {
    __shared__ int ps[SCAN_T];
    const int t = threadIdx.x;
    const int start = t * SCAN_CHUNK;

    int sum = 0;
    for (int i = 0; i < SCAN_CHUNK; i++) {
        const int idx = start + i;
        if (idx < N_NODES) sum += g_cnt[idx];
    }
    ps[t] = sum;
    __syncthreads();
    // Hillis-Steele inclusive scan over partials
    for (int o = 1; o < SCAN_T; o <<= 1) {
        int v = (t >= o) ? ps[t - o] : 0;
        __syncthreads();
        ps[t] += v;
        __syncthreads();
    }
    int base = (t > 0) ? ps[t - 1] : 0;     // exclusive prefix for this chunk
    for (int i = 0; i < SCAN_CHUNK; i++) {
        const int idx = start + i;
        if (idx < N_NODES) {
            g_off[idx] = base;
            base += g_cnt[idx];
        }
    }
}

// ---------------- K6: bucket edges into per-destination CSR -----------------
__global__ void __launch_bounds__(256)
scatter_kernel(const int* __restrict__ src, const int* __restrict__ dst) {
    const int e = blockIdx.x * blockDim.x + threadIdx.x;
    if (e >= E_EDGES) return;
    const int d = dst[e];
    const int p = atomicAdd(&g_cur[d], 1);
    const int idx = g_off[d] + p;
    g_ssrc[idx] = src[e];
    g_sw[idx]   = g_ex[e];
}

// ---------------- K7: aggregation — warp per destination node ---------------
__global__ void __launch_bounds__(256)
agg_kernel(float* __restrict__ out) {
    const int warp = (blockIdx.x * blockDim.x + threadIdx.x) >> 5;
    const int lane = threadIdx.x & 31;
    if (warp >= N_NODES) return;

    const int beg = g_off[warp];
    const int end = beg + g_cnt[warp];

    float4 acc = make_float4(0.f, 0.f, 0.f, 0.f);
    for (int j = beg; j < end; j++) {
        const float w = g_sw[j];          // broadcast across the warp
        const int   s = g_ssrc[j];
        const float4 f = reinterpret_cast<const float4*>(g_feat)[s * 32 + lane];
        acc.x = fmaf(w, f.x, acc.x);
        acc.y = fmaf(w, f.y, acc.y);
        acc.z = fmaf(w, f.z, acc.z);
        acc.w = fmaf(w, f.w, acc.w);
    }
    const float inv = 1.f / fmaxf(g_denom[warp], 1e-9f);
    acc.x *= inv; acc.y *= inv; acc.z *= inv; acc.w *= inv;
    reinterpret_cast<float4*>(out)[warp * 32 + lane] = acc;
}

// ---------------- launch ----------------------------------------------------
extern "C" void kernel_launch(void* const* d_in, const int* in_sizes, int n_in,
                              void* d_out, int out_size) {
    const float* h      = (const float*)d_in[0];
    const int*   src    = (const int*)  d_in[1];
    const int*   dst    = (const int*)  d_in[2];
    const float* W      = (const float*)d_in[3];
    const float* attn_l = (const float*)d_in[4];
    const float* attn_r = (const float*)d_in[5];
    float* out = (float*)d_out;

    gemm_kernel<<<N_NODES / 16, 128>>>(h, W);
    elr_kernel<<<(N_NODES * 32 + 255) / 256, 256>>>(attn_l, attn_r);
    init_kernel<<<(N_NODES + 255) / 256, 256>>>();
    edge_kernel<<<(E_EDGES + 255) / 256, 256>>>(src, dst);
    scan_kernel<<<1, SCAN_T>>>();
    scatter_kernel<<<(E_EDGES + 255) / 256, 256>>>(src, dst);
    agg_kernel<<<(N_NODES * 32 + 255) / 256, 256>>>(out);
}

// round 4
// speedup vs baseline: 1.4868x; 1.4868x over previous
#include <cuda_runtime.h>

#define N_NODES 100000
#define E_EDGES 1600000
#define D 128

// ---------------- scratch (static device globals; no runtime alloc) ---------
__device__ float g_feat[N_NODES * D];     // projected features (51.2 MB)
__device__ float g_el[N_NODES];           // src attention logits
__device__ float g_er[N_NODES];           // dst attention logits
__device__ int   g_cnt[N_NODES];          // in-degree histogram
__device__ int   g_off[N_NODES];          // CSR offsets
__device__ int   g_cur[N_NODES];          // scatter cursors
__device__ int2  g_sedge[E_EDGES];        // CSR slot: {src, exp-weight bits} (12.8 MB)

#define SCAN_BS 512
#define NPART ((N_NODES + SCAN_BS - 1) / SCAN_BS)   // 196
__device__ int g_part[NPART];
__device__ int g_pbase[NPART];

// ---------------- packed f32x2 helpers (sm_103a FFMA2) ----------------------
__device__ __forceinline__ unsigned long long pack2(float lo, float hi) {
    unsigned long long r;
    asm("mov.b64 %0, {%1,%2};" : "=l"(r) : "f"(lo), "f"(hi));
    return r;
}
__device__ __forceinline__ void unpack2(unsigned long long v, float& lo, float& hi) {
    asm("mov.b64 {%0,%1}, %2;" : "=f"(lo), "=f"(hi) : "l"(v));
}
__device__ __forceinline__ unsigned long long ffma2(unsigned long long a,
                                                    unsigned long long b,
                                                    unsigned long long c) {
    unsigned long long d;
    asm("fma.rn.f32x2 %0, %1, %2, %3;" : "=l"(d) : "l"(a), "l"(b), "l"(c));
    return d;
}

// ---------------- K1: feat = h @ W  (16 rows/block, packed FFMA2) -----------
__global__ void __launch_bounds__(128)
gemm_kernel(const float* __restrict__ h, const float* __restrict__ W) {
    // hs4[k][q] = rows (4q..4q+3) of the tile at column k
    __shared__ float4 hs4[D][4];
    const int t = threadIdx.x;              // output column / load column
    const int row0 = blockIdx.x * 16;

    {
        float tmp[16];
        #pragma unroll
        for (int r = 0; r < 16; r++)
            tmp[r] = h[(row0 + r) * D + t];
        #pragma unroll
        for (int q = 0; q < 4; q++)
            hs4[t][q] = make_float4(tmp[4*q], tmp[4*q+1], tmp[4*q+2], tmp[4*q+3]);
    }
    __syncthreads();

    unsigned long long acc2[8];
    #pragma unroll
    for (int j = 0; j < 8; j++) acc2[j] = 0ull;

    #pragma unroll 4
    for (int k = 0; k < D; k++) {
        const float wv = __ldg(&W[k * D + t]);
        const unsigned long long w2 = pack2(wv, wv);
        #pragma unroll
        for (int q = 0; q < 4; q++) {
            const float4 v = hs4[k][q];
            acc2[2*q]   = ffma2(pack2(v.x, v.y), w2, acc2[2*q]);
            acc2[2*q+1] = ffma2(pack2(v.z, v.w), w2, acc2[2*q+1]);
        }
    }

    #pragma unroll
    for (int j = 0; j < 8; j++) {
        float lo, hi;
        unpack2(acc2[j], lo, hi);
        g_feat[(row0 + 2*j)     * D + t] = lo;
        g_feat[(row0 + 2*j + 1) * D + t] = hi;
    }
}

// ---------------- K2: el/er = feat @ attn_{l,r}  (warp per node) ------------
__global__ void __launch_bounds__(256)
elr_kernel(const float* __restrict__ attn_l, const float* __restrict__ attn_r) {
    const int warp = (blockIdx.x * blockDim.x + threadIdx.x) >> 5;
    const int lane = threadIdx.x & 31;
    if (warp >= N_NODES) return;

    const float4 f  = reinterpret_cast<const float4*>(g_feat)[warp * 32 + lane];
    const float4 al = reinterpret_cast<const float4*>(attn_l)[lane];
    const float4 ar = reinterpret_cast<const float4*>(attn_r)[lane];
    float sl = f.x * al.x + f.y * al.y + f.z * al.z + f.w * al.w;
    float sr = f.x * ar.x + f.y * ar.y + f.z * ar.z + f.w * ar.w;
    #pragma unroll
    for (int o = 16; o; o >>= 1) {
        sl += __shfl_down_sync(0xffffffffu, sl, o);
        sr += __shfl_down_sync(0xffffffffu, sr, o);
    }
    if (lane == 0) { g_el[warp] = sl; g_er[warp] = sr; }
}

// ---------------- K3: zero histogram ----------------------------------------
__global__ void __launch_bounds__(256)
init_kernel() {
    const int i = blockIdx.x * blockDim.x + threadIdx.x;
    if (i < N_NODES) g_cnt[i] = 0;
}

// ---------------- K4: in-degree histogram -----------------------------------
__global__ void __launch_bounds__(256)
hist_kernel(const int* __restrict__ dst) {
    const int e = blockIdx.x * blockDim.x + threadIdx.x;
    if (e < E_EDGES) atomicAdd(&g_cnt[dst[e]], 1);
}

// ---------------- K5a/b/c: hierarchical exclusive scan ----------------------
__global__ void __launch_bounds__(SCAN_BS)
scanA_kernel() {
    __shared__ int sh[SCAN_BS];
    const int t = threadIdx.x;
    const int i = blockIdx.x * SCAN_BS + t;
    sh[t] = (i < N_NODES) ? g_cnt[i] : 0;
    __syncthreads();
    #pragma unroll
    for (int o = SCAN_BS / 2; o; o >>= 1) {
        if (t < o) sh[t] += sh[t + o];
        __syncthreads();
    }
    if (t == 0) g_part[blockIdx.x] = sh[0];
}

__global__ void __launch_bounds__(256)
scanB_kernel() {
    __shared__ int sh[256];
    const int t = threadIdx.x;
    const int v = (t < NPART) ? g_part[t] : 0;
    sh[t] = v;
    __syncthreads();
    for (int o = 1; o < 256; o <<= 1) {
        const int x = (t >= o) ? sh[t - o] : 0;
        __syncthreads();
        sh[t] += x;
        __syncthreads();
    }
    if (t < NPART) g_pbase[t] = sh[t] - v;       // exclusive
}

__global__ void __launch_bounds__(SCAN_BS)
scanC_kernel() {
    __shared__ int sh[SCAN_BS];
    const int t = threadIdx.x;
    const int i = blockIdx.x * SCAN_BS + t;
    const int c = (i < N_NODES) ? g_cnt[i] : 0;
    sh[t] = c;
    __syncthreads();
    for (int o = 1; o < SCAN_BS; o <<= 1) {
        const int x = (t >= o) ? sh[t - o] : 0;
        __syncthreads();
        sh[t] += x;
        __syncthreads();
    }
    if (i < N_NODES) {
        const int off = g_pbase[blockIdx.x] + sh[t] - c;   // exclusive
        g_off[i] = off;
        g_cur[i] = off;
    }
}

// ---------------- K6: fused edge score + CSR scatter ------------------------
__global__ void __launch_bounds__(256)
scatter_kernel(const int* __restrict__ src, const int* __restrict__ dst) {
    const int e = blockIdx.x * blockDim.x + threadIdx.x;
    if (e >= E_EDGES) return;
    const int s = src[e];
    const int d = dst[e];
    float x = g_el[s] + g_er[d];
    x = (x > 0.f) ? x : 0.2f * x;            // leaky relu
    const float ex = __expf(x);              // |x| small: no max-shift needed
    const int idx = atomicAdd(&g_cur[d], 1);
    g_sedge[idx] = make_int2(s, __float_as_int(ex));
}

// ---------------- K7: aggregation — warp per destination node ---------------
__global__ void __launch_bounds__(256)
agg_kernel(float* __restrict__ out) {
    const int warp = (blockIdx.x * blockDim.x + threadIdx.x) >> 5;
    const int lane = threadIdx.x & 31;
    if (warp >= N_NODES) return;

    const int beg = g_off[warp];
    const int end = beg + g_cnt[warp];

    float4 acc = make_float4(0.f, 0.f, 0.f, 0.f);
    float den = 0.f;
    int j = beg;
    for (; j + 2 <= end; j += 2) {
        const int2 p0 = g_sedge[j];
        const int2 p1 = g_sedge[j + 1];
        const float4 f0 = __ldg(&reinterpret_cast<const float4*>(g_feat)[p0.x * 32 + lane]);
        const float4 f1 = __ldg(&reinterpret_cast<const float4*>(g_feat)[p1.x * 32 + lane]);
        const float w0 = __int_as_float(p0.y);
        const float w1 = __int_as_float(p1.y);
        den += w0 + w1;
        acc.x = fmaf(w0, f0.x, acc.x); acc.y = fmaf(w0, f0.y, acc.y);
        acc.z = fmaf(w0, f0.z, acc.z); acc.w = fmaf(w0, f0.w, acc.w);
        acc.x = fmaf(w1, f1.x, acc.x); acc.y = fmaf(w1, f1.y, acc.y);
        acc.z = fmaf(w1, f1.z, acc.z); acc.w = fmaf(w1, f1.w, acc.w);
    }
    if (j < end) {
        const int2 p = g_sedge[j];
        const float4 f = __ldg(&reinterpret_cast<const float4*>(g_feat)[p.x * 32 + lane]);
        const float w = __int_as_float(p.y);
        den += w;
        acc.x = fmaf(w, f.x, acc.x); acc.y = fmaf(w, f.y, acc.y);
        acc.z = fmaf(w, f.z, acc.z); acc.w = fmaf(w, f.w, acc.w);
    }
    const float inv = 1.f / fmaxf(den, 1e-9f);
    acc.x *= inv; acc.y *= inv; acc.z *= inv; acc.w *= inv;
    reinterpret_cast<float4*>(out)[warp * 32 + lane] = acc;
}

// ---------------- launch ----------------------------------------------------
extern "C" void kernel_launch(void* const* d_in, const int* in_sizes, int n_in,
                              void* d_out, int out_size) {
    const float* h      = (const float*)d_in[0];
    const int*   src    = (const int*)  d_in[1];
    const int*   dst    = (const int*)  d_in[2];
    const float* W      = (const float*)d_in[3];
    const float* attn_l = (const float*)d_in[4];
    const float* attn_r = (const float*)d_in[5];
    float* out = (float*)d_out;

    init_kernel   <<<(N_NODES + 255) / 256, 256>>>();
    gemm_kernel   <<<N_NODES / 16, 128>>>(h, W);
    elr_kernel    <<<(N_NODES * 32 + 255) / 256, 256>>>(attn_l, attn_r);
    hist_kernel   <<<(E_EDGES + 255) / 256, 256>>>(dst);
    scanA_kernel  <<<NPART, SCAN_BS>>>();
    scanB_kernel  <<<1, 256>>>();
    scanC_kernel  <<<NPART, SCAN_BS>>>();
    scatter_kernel<<<(E_EDGES + 255) / 256, 256>>>(src, dst);
    agg_kernel    <<<(N_NODES * 32 + 255) / 256, 256>>>(out);
}